// round 1
// baseline (speedup 1.0000x reference)
#include <cuda_runtime.h>

// Shapes (fixed by the problem):
//   x: (160, 128, 48, 48) f32, vth: (160, 3) f32, mask_rand: (160, 48, 48) f32
//   out: (160, 128, 48, 48) f32
// TIME_STEP=5, bs=32, TAU=0.5, A=1.0 (step threshold at 0), DROP_RATE=0.2,
// BLOCK_SIZE=7, LAYER=1 (so vth[:, 0]).

#define N_TOT   160
#define C_DIM   128
#define H_DIM   48
#define W_DIM   48
#define HW      (H_DIM * W_DIM)          // 2304
#define TSTEP   5
#define BS      32                        // 160 / 5
#define IMG     (C_DIM * HW)              // elements per image = 294912
#define IMG4    (IMG / 4)                 // float4 per image = 73728
#define HW4     (HW / 4)                  // float4 per spatial plane = 576
#define TOTAL4  (BS * IMG4)               // threads for main kernel = 2359296

// DropBlock mask scratch: 160 * 48 * 48 floats = 1.47 MB (allocation-free).
__device__ float g_bm[N_TOT * HW];

// ---------------------------------------------------------------------------
// Kernel 1: block mask.  bm = 1 - maxpool7x7_SAME(mask_rand < gamma)
// Separable max via shared memory; one block per image.
// ---------------------------------------------------------------------------
__global__ void block_mask_kernel(const float* __restrict__ mr) {
    __shared__ float m[HW];
    __shared__ float tmp[HW];
    const int n = blockIdx.x;
    const float gamma = (float)(0.2 / 49.0);

    for (int i = threadIdx.x; i < HW; i += blockDim.x)
        m[i] = (mr[n * HW + i] < gamma) ? 1.0f : 0.0f;
    __syncthreads();

    // Horizontal window max (radius 3, clipped = SAME with -inf pad on 0/1 data)
    for (int i = threadIdx.x; i < HW; i += blockDim.x) {
        int h = i / W_DIM, w = i - h * W_DIM;
        int w0 = max(w - 3, 0), w1 = min(w + 3, W_DIM - 1);
        float mx = 0.0f;
        for (int ww = w0; ww <= w1; ++ww) mx = fmaxf(mx, m[h * W_DIM + ww]);
        tmp[i] = mx;
    }
    __syncthreads();

    // Vertical window max, then bm = 1 - pooled
    for (int i = threadIdx.x; i < HW; i += blockDim.x) {
        int h = i / W_DIM, w = i - h * W_DIM;
        int h0 = max(h - 3, 0), h1 = min(h + 3, H_DIM - 1);
        float mx = 0.0f;
        for (int hh = h0; hh <= h1; ++hh) mx = fmaxf(mx, tmp[hh * W_DIM + w]);
        g_bm[n * HW + i] = 1.0f - mx;
    }
}

// ---------------------------------------------------------------------------
// Kernel 2: LIF recurrence.  Each thread owns one (b, c, 4-wide spatial)
// strip and iterates the 5 timesteps in registers. One read + one write per
// element of x/out -> minimal DRAM traffic.
//   u_new = (u >= v ? 0 : TAU*u) + x_t
//   out   = (u_new >= v) ? bm : 0
// ---------------------------------------------------------------------------
__global__ void __launch_bounds__(256) lif_kernel(const float4* __restrict__ x4,
                                                  const float*  __restrict__ vth,
                                                  float4* __restrict__ o4) {
    int g = blockIdx.x * blockDim.x + threadIdx.x;
    if (g >= TOTAL4) return;

    const int b  = g / IMG4;         // batch index within a timestep (0..31)
    const int i  = g - b * IMG4;     // float4 index within the (C,H,W) image
    const int sp = i % HW4;          // float4 index within the (H,W) plane

    const float4* __restrict__ bm4 = (const float4*)g_bm;

    float4 u = make_float4(0.f, 0.f, 0.f, 0.f);

#pragma unroll
    for (int t = 0; t < TSTEP; ++t) {
        const int n = t * BS + b;                 // original outer index
        const float v = __ldg(&vth[n * 3]);       // vth[:, LAYER-1], LAYER=1
        const float4 xx = x4[n * IMG4 + i];
        const float4 bm = bm4[n * HW4 + sp];

        u.x = (u.x >= v ? 0.f : 0.5f * u.x) + xx.x;
        u.y = (u.y >= v ? 0.f : 0.5f * u.y) + xx.y;
        u.z = (u.z >= v ? 0.f : 0.5f * u.z) + xx.z;
        u.w = (u.w >= v ? 0.f : 0.5f * u.w) + xx.w;

        float4 out;
        out.x = (u.x >= v) ? bm.x : 0.f;
        out.y = (u.y >= v) ? bm.y : 0.f;
        out.z = (u.z >= v) ? bm.z : 0.f;
        out.w = (u.w >= v) ? bm.w : 0.f;

        o4[n * IMG4 + i] = out;
    }
}

// ---------------------------------------------------------------------------
extern "C" void kernel_launch(void* const* d_in, const int* in_sizes, int n_in,
                              void* d_out, int out_size) {
    const float* x    = (const float*)d_in[0];
    const float* vth  = (const float*)d_in[1];
    const float* mr   = (const float*)d_in[2];
    float*       out  = (float*)d_out;

    block_mask_kernel<<<N_TOT, 256>>>(mr);

    const int threads = 256;
    const int blocks  = (TOTAL4 + threads - 1) / threads;   // 9216
    lif_kernel<<<blocks, threads>>>((const float4*)x, vth, (float4*)out);
}

// round 2
// speedup vs baseline: 1.0600x; 1.0600x over previous
#include <cuda_runtime.h>

// Shapes (fixed by the problem):
//   x: (160, 128, 48, 48) f32, vth: (160, 3) f32, mask_rand: (160, 48, 48) f32
//   out: (160, 128, 48, 48) f32
// TIME_STEP=5, bs=32, TAU=0.5, step threshold at 0, DROP_RATE=0.2,
// BLOCK_SIZE=7, LAYER=1 (vth[:, 0]).

#define N_TOT   160
#define C_DIM   128
#define H_DIM   48
#define W_DIM   48
#define HW      (H_DIM * W_DIM)          // 2304
#define TSTEP   5
#define BS      32                        // 160 / 5
#define IMG     (C_DIM * HW)              // 294912
#define IMG4    (IMG / 4)                 // 73728
#define HW4     (HW / 4)                  // 576
#define TOTAL4  (BS * IMG4)               // 2359296

// DropBlock mask scratch: 160 * 48 * 48 floats = 1.47 MB (allocation-free).
__device__ float g_bm[N_TOT * HW];

// ---------------------------------------------------------------------------
// Kernel 1: block mask.  bm = 1 - maxpool7x7_SAME(mask_rand < gamma)
// Separable max via shared memory; one 1024-thread block per image
// (latency-bound kernel: minimize per-thread loop trip count).
// ---------------------------------------------------------------------------
__global__ void __launch_bounds__(1024) block_mask_kernel(const float* __restrict__ mr) {
    __shared__ float m[HW];
    __shared__ float tmp[HW];
    const int n = blockIdx.x;
    const float gamma = (float)(0.2 / 49.0);

    for (int i = threadIdx.x; i < HW; i += 1024)
        m[i] = (mr[n * HW + i] < gamma) ? 1.0f : 0.0f;
    __syncthreads();

    // Horizontal window max (radius 3, clipped == SAME on 0/1 data)
    for (int i = threadIdx.x; i < HW; i += 1024) {
        int h = i / W_DIM, w = i - h * W_DIM;
        int w0 = max(w - 3, 0), w1 = min(w + 3, W_DIM - 1);
        float mx = 0.0f;
        for (int ww = w0; ww <= w1; ++ww) mx = fmaxf(mx, m[h * W_DIM + ww]);
        tmp[i] = mx;
    }
    __syncthreads();

    // Vertical window max, then bm = 1 - pooled
    for (int i = threadIdx.x; i < HW; i += 1024) {
        int h = i / W_DIM, w = i - h * W_DIM;
        int h0 = max(h - 3, 0), h1 = min(h + 3, H_DIM - 1);
        float mx = 0.0f;
        for (int hh = h0; hh <= h1; ++hh) mx = fmaxf(mx, tmp[hh * W_DIM + w]);
        g_bm[n * HW + i] = 1.0f - mx;
    }
}

// ---------------------------------------------------------------------------
// Kernel 2: LIF recurrence. Each thread owns one (b, c, 4-wide spatial) strip.
// ALL loads for the 5 timesteps are issued up-front (10x LDG.128 + 5 scalar)
// for maximum memory-level parallelism, then the recurrence runs in registers
// and streams the outputs with evict-first stores.
//   u_new = (u >= v ? 0 : TAU*u) + x_t ;  out = (u_new >= v) ? bm : 0
// ---------------------------------------------------------------------------
__global__ void __launch_bounds__(256) lif_kernel(const float4* __restrict__ x4,
                                                  const float*  __restrict__ vth,
                                                  float4* __restrict__ o4) {
    const int g  = blockIdx.x * blockDim.x + threadIdx.x;
    const int b  = g / IMG4;         // batch index within a timestep (0..31)
    const int i  = g - b * IMG4;     // float4 index within the (C,H,W) image
    const int sp = i % HW4;          // float4 index within the (H,W) plane

    const float4* __restrict__ bm4 = (const float4*)g_bm;

    float4 xx[TSTEP];
    float4 bm[TSTEP];
    float  v[TSTEP];

#pragma unroll
    for (int t = 0; t < TSTEP; ++t) {
        const int n = t * BS + b;
        xx[t] = __ldcs(&x4[n * IMG4 + i]);   // streamed once: evict-first
        bm[t] = __ldg(&bm4[n * HW4 + sp]);   // reused 128x: keep in L2
        v[t]  = __ldg(&vth[n * 3]);          // vth[:, LAYER-1]
    }

    float4 u = make_float4(0.f, 0.f, 0.f, 0.f);

#pragma unroll
    for (int t = 0; t < TSTEP; ++t) {
        const int n = t * BS + b;
        const float vt = v[t];

        u.x = (u.x >= vt ? 0.f : 0.5f * u.x) + xx[t].x;
        u.y = (u.y >= vt ? 0.f : 0.5f * u.y) + xx[t].y;
        u.z = (u.z >= vt ? 0.f : 0.5f * u.z) + xx[t].z;
        u.w = (u.w >= vt ? 0.f : 0.5f * u.w) + xx[t].w;

        float4 out;
        out.x = (u.x >= vt) ? bm[t].x : 0.f;
        out.y = (u.y >= vt) ? bm[t].y : 0.f;
        out.z = (u.z >= vt) ? bm[t].z : 0.f;
        out.w = (u.w >= vt) ? bm[t].w : 0.f;

        __stcs(&o4[n * IMG4 + i], out);      // never re-read: evict-first
    }
}

// ---------------------------------------------------------------------------
extern "C" void kernel_launch(void* const* d_in, const int* in_sizes, int n_in,
                              void* d_out, int out_size) {
    const float* x   = (const float*)d_in[0];
    const float* vth = (const float*)d_in[1];
    const float* mr  = (const float*)d_in[2];
    float*       out = (float*)d_out;

    block_mask_kernel<<<N_TOT, 1024>>>(mr);

    const int threads = 256;
    const int blocks  = TOTAL4 / threads;   // 9216, exact
    lif_kernel<<<blocks, threads>>>((const float4*)x, vth, (float4*)out);
}